// round 16
// baseline (speedup 1.0000x reference)
#include <cuda_runtime.h>
#include <cuda_fp16.h>
#include <cstdint>

#define M_TOTAL 8192
#define N_TOTAL 11008
#define K_TOTAL 4096
#define GROUPS 32
#define PACKED 2048

// GEMM tiling: CTA 128x128x64, 8 warps (2M x 4N), warp tile 64x32, 3 stages.
#define BM 128
#define BN 128
#define BK 64
#define STAGES 3
#define NK_TILES (K_TOTAL / BK)   // 64
#define TILES_N (N_TOTAL / BN)    // 86
#define TILES_M (M_TOTAL / BM)    // 64
#define GROUP_M 8

// SMEM: mbarriers in first 1024B, then 128B-row XOR-swizzled tiles.
#define A_BYTES (BM * 128)                 // 16384
#define B_BYTES (BN * 128)                 // 16384
#define STAGE_BYTES (A_BYTES + B_BYTES)    // 32768
#define TILE_BASE 1024
#define SMEM_TOTAL (TILE_BASE + STAGES * STAGE_BYTES)  // 99328

// Prep kernel split
#define DQ_BLOCKS ((N_TOTAL * (PACKED / 4) + 255) / 256)       // 22016
#define XC_BLOCKS ((M_TOTAL * K_TOTAL / 4) / 256)              // 32768

// Scratch: dequantized W (fp16) and converted x (fp16).
__device__ __half g_W[(size_t)N_TOTAL * K_TOTAL];  // ~90 MB
__device__ __half g_X[(size_t)M_TOTAL * K_TOTAL];  // ~67 MB

__device__ __forceinline__ uint32_t smem_u32(const void* p) {
    uint32_t a;
    asm("{ .reg .u64 t; cvta.to.shared.u64 t, %1; cvt.u32.u64 %0, t; }"
        : "=r"(a) : "l"(p));
    return a;
}

__device__ __forceinline__ void cp_async16(uint32_t dst, const void* src) {
    asm volatile("cp.async.cg.shared.global [%0], [%1], 16;\n" :: "r"(dst), "l"(src));
}

__device__ __forceinline__ void ldsm_x4(uint32_t (&r)[4], uint32_t addr) {
    asm volatile("ldmatrix.sync.aligned.m8n8.x4.shared.b16 {%0,%1,%2,%3}, [%4];"
                 : "=r"(r[0]), "=r"(r[1]), "=r"(r[2]), "=r"(r[3]) : "r"(addr));
}

__device__ __forceinline__ void mbar_init(uint32_t addr, uint32_t count) {
    asm volatile("mbarrier.init.shared.b64 [%0], %1;" :: "r"(addr), "r"(count) : "memory");
}

__device__ __forceinline__ void mbar_arrive(uint32_t addr) {
    asm volatile("mbarrier.arrive.shared.b64 _, [%0];" :: "r"(addr) : "memory");
}

// NOTE: .noinc is load-bearing. The default variant increments the expected
// count at issue and decrements at completion (net zero) -> the barrier never
// completes -> deadlock (observed in R15). .noinc consumes one of the
// pre-initialized 256 counts when this thread's prior cp.asyncs complete.
__device__ __forceinline__ void cpasync_mbar_arrive_noinc(uint32_t addr) {
    asm volatile("cp.async.mbarrier.arrive.noinc.shared.b64 [%0];" :: "r"(addr) : "memory");
}

__device__ __forceinline__ void mbar_wait(uint32_t addr, uint32_t parity) {
    uint32_t done;
    asm volatile(
        "{\n\t.reg .pred p;\n\t"
        "mbarrier.try_wait.parity.shared.b64 p, [%1], %2;\n\t"
        "selp.b32 %0, 1, 0, p;\n\t}"
        : "=r"(done) : "r"(addr), "r"(parity) : "memory");
    while (!done) {
        asm volatile(
            "{\n\t.reg .pred p;\n\t"
            "mbarrier.try_wait.parity.shared.b64 p, [%1], %2, 0x989680;\n\t"
            "selp.b32 %0, 1, 0, p;\n\t}"
            : "=r"(done) : "r"(addr), "r"(parity) : "memory");
    }
}

// ---------------------------------------------------------------------------
// Kernel 1: merged prep — int4 dequant -> fp16 W, and x fp32 -> fp16.
// ---------------------------------------------------------------------------
__global__ void prep_kernel(const int4* __restrict__ wp4,
                            const float* __restrict__ scale,
                            const float* __restrict__ zp,
                            const float* __restrict__ x) {
    const int b = blockIdx.x;
    if (b < DQ_BLOCKS) {
        int c = b * 256 + threadIdx.x;
        if (c >= N_TOTAL * (PACKED / 4)) return;
        int o = c >> 9;
        int pc = c & 511;
        int g = pc >> 4;
        float s = __ldg(scale + o * GROUPS + g);
        float z = __ldg(zp + o * GROUPS + g);
        int4 v = __ldcs(wp4 + c);
        uint4 outv;
        __half2 h0 = __floats2half2_rn(((float)((v.x >> 4) & 15) - z) * s,
                                       ((float)(v.x & 15) - z) * s);
        __half2 h1 = __floats2half2_rn(((float)((v.y >> 4) & 15) - z) * s,
                                       ((float)(v.y & 15) - z) * s);
        __half2 h2 = __floats2half2_rn(((float)((v.z >> 4) & 15) - z) * s,
                                       ((float)(v.z & 15) - z) * s);
        __half2 h3 = __floats2half2_rn(((float)((v.w >> 4) & 15) - z) * s,
                                       ((float)(v.w & 15) - z) * s);
        outv.x = *(uint32_t*)&h0;
        outv.y = *(uint32_t*)&h1;
        outv.z = *(uint32_t*)&h2;
        outv.w = *(uint32_t*)&h3;
        __stcs(reinterpret_cast<uint4*>(g_W) + c, outv);
    } else {
        int i = (b - DQ_BLOCKS) * 256 + threadIdx.x;
        float4 f = __ldcs(reinterpret_cast<const float4*>(x) + i);
        __half2 h0 = __floats2half2_rn(f.x, f.y);
        __half2 h1 = __floats2half2_rn(f.z, f.w);
        uint2 o;
        o.x = *(uint32_t*)&h0;
        o.y = *(uint32_t*)&h1;
        __stcs(reinterpret_cast<uint2*>(g_X) + i, o);
    }
}

// ---------------------------------------------------------------------------
// Kernel 2: GEMM  out[m][n] = sum_k X[m][k] * W[n][k] + bias[n]
// mbarrier producer/consumer pipeline: no __syncthreads in the main loop,
// warps decouple up to the 3-stage depth.
// full(s): count 256, cp.async.mbarrier.arrive.noinc per thread per fill.
// empty(s): count 8, lane 0 per warp arrives after the warp's last LDSM.
// ---------------------------------------------------------------------------
__global__ void __launch_bounds__(256, 2)
gemm_kernel(float* __restrict__ out, const float* __restrict__ bias) {
    extern __shared__ __half smem[];
    const uint32_t sb = smem_u32(smem);

    const int tid  = threadIdx.x;
    const int lane = tid & 31;
    const int warp = tid >> 5;
    const int wm = (warp & 1) * 64;
    const int wn = (warp >> 1) * 32;

    // Supertile raster: groups of GROUP_M m-tiles; within a group, m-fast.
    const int bid = blockIdx.x;
    const int group = bid / (TILES_N * GROUP_M);
    const int rem   = bid % (TILES_N * GROUP_M);
    const int m0 = (group * GROUP_M + (rem % GROUP_M)) * BM;
    const int n0 = (rem / GROUP_M) * BN;

    // mbarriers: full(s) at sb + s*16, empty(s) at sb + s*16 + 8.
    if (tid == 0) {
#pragma unroll
        for (int s = 0; s < STAGES; s++) {
            mbar_init(sb + s * 16, 256);      // full
            mbar_init(sb + s * 16 + 8, 8);    // empty
        }
    }
    __syncthreads();

    float acc[4][4][4];
#pragma unroll
    for (int mi = 0; mi < 4; mi++)
#pragma unroll
        for (int ni = 0; ni < 4; ni++)
#pragma unroll
            for (int e = 0; e < 4; e++) acc[mi][ni][e] = 0.0f;

    // Hoisted loader addressing.
    uint32_t s_off[4];
    const __half* a_src[4];
    const __half* b_src[4];
    {
        const __half* Ag = g_X + (size_t)m0 * K_TOTAL;
        const __half* Bg = g_W + (size_t)n0 * K_TOTAL;
#pragma unroll
        for (int i = 0; i < 4; i++) {
            int c = tid + (i << 8);
            int row = c >> 3, seg = c & 7;
            s_off[i] = (uint32_t)(row * 128) +
                       (((uint32_t)(seg * 16)) ^ (((uint32_t)row & 7u) << 4));
            a_src[i] = Ag + (size_t)row * K_TOTAL + seg * 8;
            b_src[i] = Bg + (size_t)row * K_TOTAL + seg * 8;
        }
    }

    auto load_stage = [&](int s, int k0) {
        const uint32_t base = sb + TILE_BASE + (uint32_t)s * STAGE_BYTES;
#pragma unroll
        for (int i = 0; i < 4; i++)
            cp_async16(base + s_off[i], a_src[i] + k0);
#pragma unroll
        for (int i = 0; i < 4; i++)
            cp_async16(base + (uint32_t)A_BYTES + s_off[i], b_src[i] + k0);
        cpasync_mbar_arrive_noinc(sb + s * 16);  // arrives when this thread's cps land
    };

    load_stage(0, 0);
    load_stage(1, BK);

    // Per-lane ldmatrix addressing (loop-invariant).
    const int r16 = lane & 15;
    const uint32_t hi16 = (uint32_t)((lane >> 4) * 16);
    const uint32_t xorv = ((uint32_t)(r16 & 7)) << 4;
    const uint32_t wrot = (uint32_t)(warp & 3);
    uint32_t a_row[4], b_row[2], colb[4];
#pragma unroll
    for (int mi = 0; mi < 4; mi++)
        a_row[mi] = (uint32_t)((wm + mi * 16 + r16) * 128);
#pragma unroll
    for (int ng = 0; ng < 2; ng++)
        b_row[ng] = (uint32_t)A_BYTES + (uint32_t)((wn + ng * 16 + r16) * 128);
#pragma unroll
    for (int j = 0; j < 4; j++)
        colb[j] = (((((uint32_t)j + wrot) & 3u) << 5) + hi16) ^ xorv;

    auto do_chunk = [&](uint32_t st, int j) {
        const uint32_t cb = colb[j];
        uint32_t a[4][4];
#pragma unroll
        for (int mi = 0; mi < 4; mi++)
            ldsm_x4(a[mi], st + a_row[mi] + cb);
        uint32_t b[4][2];
#pragma unroll
        for (int ng = 0; ng < 2; ng++) {
            uint32_t r[4];
            ldsm_x4(r, st + b_row[ng] + cb);
            b[ng * 2 + 0][0] = r[0]; b[ng * 2 + 0][1] = r[2];
            b[ng * 2 + 1][0] = r[1]; b[ng * 2 + 1][1] = r[3];
        }
#pragma unroll
        for (int mi = 0; mi < 4; mi++)
#pragma unroll
            for (int ni = 0; ni < 4; ni++) {
                asm volatile(
                    "mma.sync.aligned.m16n8k16.row.col.f32.f16.f16.f32 "
                    "{%0,%1,%2,%3}, {%4,%5,%6,%7}, {%8,%9}, {%0,%1,%2,%3};\n"
                    : "+f"(acc[mi][ni][0]), "+f"(acc[mi][ni][1]),
                      "+f"(acc[mi][ni][2]), "+f"(acc[mi][ni][3])
                    : "r"(a[mi][0]), "r"(a[mi][1]), "r"(a[mi][2]), "r"(a[mi][3]),
                      "r"(b[ni][0]), "r"(b[ni][1]));
            }
    };

    uint32_t fph = 0, eph = 0;   // per-stage phase bits (bit s)
    int s = 0;
    for (int i = 0; i < NK_TILES; i++) {
        // Consume: wait stage s full for this round.
        mbar_wait(sb + s * 16, (fph >> s) & 1u);
        fph ^= (1u << s);

        const uint32_t st = sb + TILE_BASE + (uint32_t)s * STAGE_BYTES;
        do_chunk(st, 0);

        // Produce: refill slot (i+2)%3 (the slot consumed at i-1).
        if (i + 2 < NK_TILES) {
            const int sp = (s == 0) ? 2 : s - 1;   // == (i+2)%3
            if (i >= 1) {                          // fill round >= 1: WAR wait
                mbar_wait(sb + sp * 16 + 8, (eph >> sp) & 1u);
                eph ^= (1u << sp);
            }
            load_stage(sp, (i + 2) * BK);
        }

#pragma unroll
        for (int j = 1; j < 4; j++) do_chunk(st, j);

        // Release: this warp is done reading stage s.
        __syncwarp();
        if (lane == 0) mbar_arrive(sb + s * 16 + 8);

        s = (s == STAGES - 1) ? 0 : s + 1;
    }

    // Epilogue: bias (hoisted) + streaming fp32 stores.
    const int r  = lane >> 2;
    const int c2 = (lane & 3) * 2;
    float bc0[4], bc1[4];
#pragma unroll
    for (int ni = 0; ni < 4; ni++) {
        bc0[ni] = __ldg(bias + n0 + wn + ni * 8 + c2);
        bc1[ni] = __ldg(bias + n0 + wn + ni * 8 + c2 + 1);
    }
#pragma unroll
    for (int mi = 0; mi < 4; mi++) {
        const int row = m0 + wm + mi * 16 + r;
        float* o0 = out + (size_t)row * N_TOTAL + n0 + wn;
        float* o1 = o0 + (size_t)8 * N_TOTAL;
#pragma unroll
        for (int ni = 0; ni < 4; ni++) {
            const int col = ni * 8 + c2;
            __stcs(reinterpret_cast<float2*>(o0 + col),
                   make_float2(acc[mi][ni][0] + bc0[ni], acc[mi][ni][1] + bc1[ni]));
            __stcs(reinterpret_cast<float2*>(o1 + col),
                   make_float2(acc[mi][ni][2] + bc0[ni], acc[mi][ni][3] + bc1[ni]));
        }
    }
}

// ---------------------------------------------------------------------------
// Launch
// ---------------------------------------------------------------------------
extern "C" void kernel_launch(void* const* d_in, const int* in_sizes, int n_in,
                              void* d_out, int out_size) {
    const float* x     = (const float*)d_in[0];
    const int*   wp    = (const int*)d_in[1];
    const float* scale = (const float*)d_in[2];
    const float* zp    = (const float*)d_in[3];
    const float* bias  = (const float*)d_in[4];
    float* out = (float*)d_out;

    prep_kernel<<<DQ_BLOCKS + XC_BLOCKS, 256>>>((const int4*)wp, scale, zp, x);

    cudaFuncSetAttribute(gemm_kernel,
                         cudaFuncAttributeMaxDynamicSharedMemorySize, SMEM_TOTAL);
    gemm_kernel<<<TILES_N * TILES_M, 256, SMEM_TOTAL>>>(out, bias);
}